// round 12
// baseline (speedup 1.0000x reference)
#include <cuda_runtime.h>
#include <math.h>
#include <stdint.h>

#define NN    50000
#define FH    128      // H*C
#define NH    4
#define EMAX  800000
#define NEG   0.2f
#define NBMAX 256      // >= ceil(NN/256) scan blocks
#define LOG2E 1.44269504088896f

// ---------------- scratch (static device globals; no runtime alloc) --------
__device__ float  g_xp[NN * FH];         // projected features fp32 [N][128]
__device__ float  g_asrc[NN * NH];       // prescaled by log2e
__device__ float  g_adst[NN * NH];       // prescaled by log2e
__device__ int    g_deg[NN];             // real-edge counts; re-zeroed in scan
__device__ int    g_ord[EMAX];           // per-edge ordinal within its dst row
__device__ int    g_rowptr[NN + 1];
__device__ int    g_bval[NBMAX];
__device__ volatile int g_bflag[NBMAX];
__device__ int    g_hdone, g_sdone;      // phase counters; reset by k_agg
__device__ int    g_csr[EMAX + NN];

// ---------------- helpers ---------------------------------------------------
__device__ __forceinline__ void f2tf32x2(float f, uint32_t& hi, uint32_t& lo) {
    asm("cvt.rna.tf32.f32 %0, %1;" : "=r"(hi) : "f"(f));
    float d = f - __uint_as_float(hi);
    asm("cvt.rna.tf32.f32 %0, %1;" : "=r"(lo) : "f"(d));
}

__device__ __forceinline__ void mma_tf32(float* c, const uint32_t* a, const uint32_t* b) {
    asm volatile(
        "mma.sync.aligned.m16n8k8.row.col.f32.tf32.tf32.f32 "
        "{%0,%1,%2,%3}, {%4,%5,%6,%7}, {%8,%9}, {%0,%1,%2,%3};"
        : "+f"(c[0]), "+f"(c[1]), "+f"(c[2]), "+f"(c[3])
        : "r"(a[0]), "r"(a[1]), "r"(a[2]), "r"(a[3]), "r"(b[0]), "r"(b[1]));
}

__device__ __forceinline__ void ffma2(unsigned long long& acc, unsigned long long v,
                                      unsigned long long w2) {
    asm("fma.rn.f32x2 %0, %1, %2, %0;" : "+l"(acc) : "l"(v), "l"(w2));
}

__device__ __forceinline__ float ex2(float a) {
    float r;
    asm("ex2.approx.f32 %0, %1;" : "=f"(r) : "f"(a));
    return r;
}

// ---------------- GEMM: xp = x @ W^T via 3xTF32 tensor cores ----------------
// __launch_bounds__(256,2): cap regs at 128 -> 2 CTAs/SM (16 warps) for
// latency hiding; acc array stays register-resident.
#define XP 20
#define WP 136
__global__ __launch_bounds__(256, 2) void k_gemm(
    const float* __restrict__ x, const float* __restrict__ W,
    const float* __restrict__ attS, const float* __restrict__ attD, int n)
{
    __shared__ float xsh[128 * XP], xsl[128 * XP];
    __shared__ float wth[16 * WP],  wtl[16 * WP];
    __shared__ float sAttS[128], sAttD[128];
    __shared__ float sAs[128 * 4], sAd[128 * 4];

    int t = threadIdx.x;
    // prescale by log2e: exp(leaky(z)) == exp2(leaky(z*log2e)) (leaky pos-homog.)
    if (t < 128) { sAttS[t] = attS[t] * LOG2E; sAttD[t] = attD[t] * LOG2E; }

    int row0 = blockIdx.x * 128;
    int wid = t >> 5, lane = t & 31;
    int wm = wid >> 1, wn = wid & 1;
    int g = lane >> 2, q4 = lane & 3;

    float acc[2][8][4];
#pragma unroll
    for (int mt = 0; mt < 2; mt++)
#pragma unroll
        for (int nt = 0; nt < 8; nt++)
#pragma unroll
            for (int c = 0; c < 4; c++) acc[mt][nt][c] = 0.f;

    for (int kc = 0; kc < 128; kc += 16) {
#pragma unroll
        for (int j = 0; j < 2; j++) {
            int idx = t + 256 * j;
            int r = idx >> 2, q = idx & 3;
            float4 v = make_float4(0.f, 0.f, 0.f, 0.f);
            if (row0 + r < n) v = *(const float4*)(x + (size_t)(row0 + r) * 128 + kc + q * 4);
            uint32_t h0, l0, h1, l1, h2, l2, h3, l3;
            f2tf32x2(v.x, h0, l0); f2tf32x2(v.y, h1, l1);
            f2tf32x2(v.z, h2, l2); f2tf32x2(v.w, h3, l3);
            float* ph = xsh + r * XP + q * 4;
            float* pl = xsl + r * XP + q * 4;
            ph[0] = __uint_as_float(h0); ph[1] = __uint_as_float(h1);
            ph[2] = __uint_as_float(h2); ph[3] = __uint_as_float(h3);
            pl[0] = __uint_as_float(l0); pl[1] = __uint_as_float(l1);
            pl[2] = __uint_as_float(l2); pl[3] = __uint_as_float(l3);
        }
#pragma unroll
        for (int j = 0; j < 2; j++) {
            int idx = t + 256 * j;
            int oc = idx >> 2, q = idx & 3;
            float4 v = *(const float4*)(W + (size_t)oc * 128 + kc + q * 4);
            uint32_t h0, l0, h1, l1, h2, l2, h3, l3;
            f2tf32x2(v.x, h0, l0); f2tf32x2(v.y, h1, l1);
            f2tf32x2(v.z, h2, l2); f2tf32x2(v.w, h3, l3);
            wth[(q * 4 + 0) * WP + oc] = __uint_as_float(h0);
            wth[(q * 4 + 1) * WP + oc] = __uint_as_float(h1);
            wth[(q * 4 + 2) * WP + oc] = __uint_as_float(h2);
            wth[(q * 4 + 3) * WP + oc] = __uint_as_float(h3);
            wtl[(q * 4 + 0) * WP + oc] = __uint_as_float(l0);
            wtl[(q * 4 + 1) * WP + oc] = __uint_as_float(l1);
            wtl[(q * 4 + 2) * WP + oc] = __uint_as_float(l2);
            wtl[(q * 4 + 3) * WP + oc] = __uint_as_float(l3);
        }
        __syncthreads();

#pragma unroll
        for (int kk = 0; kk < 16; kk += 8) {
            uint32_t ah[2][4], al[2][4];
#pragma unroll
            for (int mt = 0; mt < 2; mt++) {
                int r = wm * 32 + mt * 16 + g;
                int b0 = r * XP + kk + q4;
                ah[mt][0] = __float_as_uint(xsh[b0]);
                ah[mt][1] = __float_as_uint(xsh[b0 + 8 * XP]);
                ah[mt][2] = __float_as_uint(xsh[b0 + 4]);
                ah[mt][3] = __float_as_uint(xsh[b0 + 8 * XP + 4]);
                al[mt][0] = __float_as_uint(xsl[b0]);
                al[mt][1] = __float_as_uint(xsl[b0 + 8 * XP]);
                al[mt][2] = __float_as_uint(xsl[b0 + 4]);
                al[mt][3] = __float_as_uint(xsl[b0 + 8 * XP + 4]);
            }
#pragma unroll
            for (int nt = 0; nt < 8; nt++) {
                int col = wn * 64 + nt * 8 + g;
                int kb = (kk + q4) * WP + col;
                uint32_t bh[2], bl[2];
                bh[0] = __float_as_uint(wth[kb]);
                bh[1] = __float_as_uint(wth[kb + 4 * WP]);
                bl[0] = __float_as_uint(wtl[kb]);
                bl[1] = __float_as_uint(wtl[kb + 4 * WP]);
#pragma unroll
                for (int mt = 0; mt < 2; mt++) {
                    mma_tf32(acc[mt][nt], ah[mt], bh);
                    mma_tf32(acc[mt][nt], ah[mt], bl);
                    mma_tf32(acc[mt][nt], al[mt], bh);
                }
            }
        }
        __syncthreads();
    }

#pragma unroll
    for (int mt = 0; mt < 2; mt++) {
#pragma unroll
        for (int half = 0; half < 2; half++) {
            int rl = wm * 32 + mt * 16 + half * 8 + g;
            int r = row0 + rl;
            float ps0 = 0.f, pd0 = 0.f, ps1 = 0.f, pd1 = 0.f;
#pragma unroll
            for (int nt = 0; nt < 8; nt++) {
                int cbase = wn * 64 + nt * 8 + q4 * 2;
                float v0 = acc[mt][nt][half * 2 + 0];
                float v1 = acc[mt][nt][half * 2 + 1];
                float as0 = sAttS[cbase], as1 = sAttS[cbase + 1];
                float ad0 = sAttD[cbase], ad1 = sAttD[cbase + 1];
                if (nt < 4) { ps0 += v0 * as0 + v1 * as1; pd0 += v0 * ad0 + v1 * ad1; }
                else        { ps1 += v0 * as0 + v1 * as1; pd1 += v0 * ad0 + v1 * ad1; }
                if (r < n)
                    *(float2*)(g_xp + (size_t)r * 128 + cbase) = make_float2(v0, v1);
            }
            ps0 += __shfl_xor_sync(0xffffffffu, ps0, 1); ps0 += __shfl_xor_sync(0xffffffffu, ps0, 2);
            ps1 += __shfl_xor_sync(0xffffffffu, ps1, 1); ps1 += __shfl_xor_sync(0xffffffffu, ps1, 2);
            pd0 += __shfl_xor_sync(0xffffffffu, pd0, 1); pd0 += __shfl_xor_sync(0xffffffffu, pd0, 2);
            pd1 += __shfl_xor_sync(0xffffffffu, pd1, 1); pd1 += __shfl_xor_sync(0xffffffffu, pd1, 2);
            if (q4 == 0) {
                sAs[rl * 4 + wn * 2 + 0] = ps0;
                sAs[rl * 4 + wn * 2 + 1] = ps1;
                sAd[rl * 4 + wn * 2 + 0] = pd0;
                sAd[rl * 4 + wn * 2 + 1] = pd1;
            }
        }
    }
    __syncthreads();
    if (t < 128 && row0 + t < n) {
        *(float4*)(g_asrc + (size_t)(row0 + t) * 4) = *(const float4*)(sAs + t * 4);
        *(float4*)(g_adst + (size_t)(row0 + t) * 4) = *(const float4*)(sAd + t * 4);
    }
}

// ---------------- fused CSR build: hist | scan | scatter phases -------------
__global__ __launch_bounds__(256) void k_csr(
    const int* __restrict__ src, const int* __restrict__ dst,
    int n, int E, int nhist, int nscan)
{
    __shared__ int s[256];
    int t = threadIdx.x, b = blockIdx.x;

    if (b < nhist) {
        if (b == 0 && t < NBMAX) g_bflag[t] = 0;
        int e = b * 256 + t;
        if (e < E) {
            int d = __ldcs(dst + e);
            g_ord[e] = atomicAdd(&g_deg[d], 1);
        }
        __syncthreads();
        if (t == 0) { __threadfence(); atomicAdd(&g_hdone, 1); }
        return;
    }

    if (b < nhist + nscan) {
        if (t == 0) {
            while (*(volatile int*)&g_hdone < nhist) { }
            __threadfence();
        }
        __syncthreads();

        int sb = b - nhist;
        int i = sb * 256 + t;
        int v = 0;
        if (i < n) { v = g_deg[i] + 1; g_deg[i] = 0; }
        s[t] = v;
        __syncthreads();
#pragma unroll
        for (int off = 1; off < 256; off <<= 1) {
            int u = (t >= off) ? s[t - off] : 0;
            __syncthreads();
            s[t] += u;
            __syncthreads();
        }
        int incl = s[t];
        int agg  = s[255];
        if (t == 255) {
            g_bval[sb] = agg;
            __threadfence();
            g_bflag[sb] = 1;
        }
        int part = 0;
        for (int j = t; j < sb; j += 256) {
            while (g_bflag[j] == 0) { }
            part += *(volatile int*)&g_bval[j];
        }
        __syncthreads();
        s[t] = part;
        __syncthreads();
#pragma unroll
        for (int off = 128; off > 0; off >>= 1) {
            if (t < off) s[t] += s[t + off];
            __syncthreads();
        }
        int excl0 = s[0];
        if (i < n) g_rowptr[i] = excl0 + incl - v;
        if (sb == nscan - 1 && t == 255) g_rowptr[n] = excl0 + agg;
        __syncthreads();
        if (t == 0) { __threadfence(); atomicAdd(&g_sdone, 1); }
        return;
    }

    if (t == 0) {
        while (*(volatile int*)&g_sdone < nscan) { }
        __threadfence();
    }
    __syncthreads();

    int e = (b - nhist - nscan) * 256 + t;
    int total = E + n;
    if (e >= total) return;
    if (e < E) {
        int d = __ldcs(dst + e);
        int p = g_rowptr[d] + __ldcs(g_ord + e);
        g_csr[p] = __ldcs(src + e);
    } else {
        int i = e - E;
        g_csr[g_rowptr[i + 1] - 1] = i;      // self loop in last slot
    }
}

// ---------------- aggregation: one warp per destination node ----------------
__global__ __launch_bounds__(256) void k_agg(
    const float* __restrict__ bias, float* __restrict__ out, int n)
{
    // reset fused-CSR phase counters for the next graph replay
    if (blockIdx.x == 0 && threadIdx.x == 0) { g_hdone = 0; g_sdone = 0; }

    int warp = (blockIdx.x * blockDim.x + threadIdx.x) >> 5;
    int lane = threadIdx.x & 31;
    if (warp >= n) return;
    int nd = warp;
    int h = lane >> 3;

    int begin = g_rowptr[nd], end = g_rowptr[nd + 1];
    float adh = g_adst[nd * 4 + h];

    unsigned long long acc01 = 0ull, acc23 = 0ull;   // packed f32x2 accumulators
    float den = 0.f;
    const float* xpb = g_xp + lane * 4;

    int i = begin;
    // head: align to 16B so the int4 csr loads below are aligned
    for (; i < end && (i & 3); i++) {
        int s0 = g_csr[i];
        float a0 = g_asrc[s0 * 4 + h] + adh;
        ulonglong2 u0 = *(const ulonglong2*)(xpb + (size_t)s0 * 128);
        a0 = fmaxf(a0, NEG * a0);
        float w0 = ex2(a0);
        unsigned long long ww;
        asm("mov.b64 %0, {%1, %1};" : "=l"(ww) : "f"(w0));
        ffma2(acc01, u0.x, ww); ffma2(acc23, u0.y, ww);
        den += w0;
    }
    for (; i + 4 <= end; i += 4) {
        int4 sv = *(const int4*)(g_csr + i);          // 1x LDG.128 for 4 edges
        float a0 = g_asrc[sv.x * 4 + h] + adh;
        float a1 = g_asrc[sv.y * 4 + h] + adh;
        float a2 = g_asrc[sv.z * 4 + h] + adh;
        float a3 = g_asrc[sv.w * 4 + h] + adh;
        ulonglong2 u0 = *(const ulonglong2*)(xpb + (size_t)sv.x * 128);
        ulonglong2 u1 = *(const ulonglong2*)(xpb + (size_t)sv.y * 128);
        ulonglong2 u2 = *(const ulonglong2*)(xpb + (size_t)sv.z * 128);
        ulonglong2 u3 = *(const ulonglong2*)(xpb + (size_t)sv.w * 128);
        a0 = fmaxf(a0, NEG * a0);
        a1 = fmaxf(a1, NEG * a1);
        a2 = fmaxf(a2, NEG * a2);
        a3 = fmaxf(a3, NEG * a3);
        float w0 = ex2(a0), w1 = ex2(a1), w2 = ex2(a2), w3 = ex2(a3);
        unsigned long long ww;
        asm("mov.b64 %0, {%1, %1};" : "=l"(ww) : "f"(w0));
        ffma2(acc01, u0.x, ww); ffma2(acc23, u0.y, ww);
        asm("mov.b64 %0, {%1, %1};" : "=l"(ww) : "f"(w1));
        ffma2(acc01, u1.x, ww); ffma2(acc23, u1.y, ww);
        asm("mov.b64 %0, {%1, %1};" : "=l"(ww) : "f"(w2));
        ffma2(acc01, u2.x, ww); ffma2(acc23, u2.y, ww);
        asm("mov.b64 %0, {%1, %1};" : "=l"(ww) : "f"(w3));
        ffma2(acc01, u3.x, ww); ffma2(acc23, u3.y, ww);
        den += (w0 + w1) + (w2 + w3);
    }
    for (; i < end; i++) {
        int s0 = g_csr[i];
        float a0 = g_asrc[s0 * 4 + h] + adh;
        ulonglong2 u0 = *(const ulonglong2*)(xpb + (size_t)s0 * 128);
        a0 = fmaxf(a0, NEG * a0);
        float w0 = ex2(a0);
        unsigned long long ww;
        asm("mov.b64 %0, {%1, %1};" : "=l"(ww) : "f"(w0));
        ffma2(acc01, u0.x, ww); ffma2(acc23, u0.y, ww);
        den += w0;
    }

    float ax, ay, az, aw;
    asm("mov.b64 {%0, %1}, %2;" : "=f"(ax), "=f"(ay) : "l"(acc01));
    asm("mov.b64 {%0, %1}, %2;" : "=f"(az), "=f"(aw) : "l"(acc23));

    float inv = 1.0f / (den + 1e-16f);
    float4 bb = ((const float4*)bias)[lane];
    float4 o;
    o.x = ax * inv + bb.x;
    o.y = ay * inv + bb.y;
    o.z = az * inv + bb.z;
    o.w = aw * inv + bb.w;
    o.x = o.x > 0.f ? o.x : (__expf(o.x) - 1.f);
    o.y = o.y > 0.f ? o.y : (__expf(o.y) - 1.f);
    o.z = o.z > 0.f ? o.z : (__expf(o.z) - 1.f);
    o.w = o.w > 0.f ? o.w : (__expf(o.w) - 1.f);
    ((float4*)out)[(size_t)nd * 32 + lane] = o;
}

// ---------------- launch: GEMM overlapped with fused CSR build --------------
extern "C" void kernel_launch(void* const* d_in, const int* in_sizes, int n_in,
                              void* d_out, int out_size)
{
    const float* x    = (const float*)d_in[0];
    const float* W    = (const float*)d_in[1];
    const float* attS = (const float*)d_in[2];
    const float* attD = (const float*)d_in[3];
    const float* bias = (const float*)d_in[4];
    const int*   ei   = (const int*)d_in[5];

    int n = in_sizes[0] / FH;        // 50000
    int E = in_sizes[5] / 2;         // 800000
    const int* src = ei;
    const int* dst = ei + E;

    int nhist = (E + 255) / 256;                 // 3125
    int nscan = (n + 255) / 256;                 // 196
    int nscat = (E + n + 255) / 256;             // 3321

    // host-side resources, created once (host objects only; no device memory)
    static cudaStream_t s_side = nullptr;
    static cudaEvent_t  ev_fork = nullptr, ev_join = nullptr;
    if (s_side == nullptr) {
        cudaStreamCreateWithFlags(&s_side, cudaStreamNonBlocking);
        cudaEventCreateWithFlags(&ev_fork, cudaEventDisableTiming);
        cudaEventCreateWithFlags(&ev_join, cudaEventDisableTiming);
    }

    // fork: GEMM on side stream, fused CSR build on main stream
    cudaEventRecord(ev_fork, 0);
    cudaStreamWaitEvent(s_side, ev_fork, 0);
    k_gemm<<<(n + 127) / 128, 256, 0, s_side>>>(x, W, attS, attD, n);
    cudaEventRecord(ev_join, s_side);

    k_csr<<<nhist + nscan + nscat, 256>>>(src, dst, n, E, nhist, nscan);

    // join: aggregation needs both GEMM outputs and CSR
    cudaStreamWaitEvent(0, ev_join, 0);
    k_agg<<<(n * 32 + 255) / 256, 256>>>(bias, (float*)d_out, n);
}

// round 13
// speedup vs baseline: 1.3141x; 1.3141x over previous
#include <cuda_runtime.h>
#include <math.h>
#include <stdint.h>

#define NN    50000
#define FH    128      // H*C
#define NH    4
#define EMAX  800000
#define NEG   0.2f
#define NBMAX 256      // >= ceil(NN/256) scan blocks
#define LOG2E 1.44269504088896f

// ---------------- scratch (static device globals; no runtime alloc) --------
__device__ float  g_xp[NN * FH];         // projected features fp32 [N][128]
__device__ float  g_asrc[NN * NH];       // prescaled by log2e
__device__ float  g_adst[NN * NH];       // prescaled by log2e
__device__ int    g_deg[NN];             // real-edge counts; re-zeroed in scan
__device__ int    g_ord[EMAX];           // per-edge ordinal within its dst row
__device__ int    g_rowptr[NN + 1];
__device__ int    g_bval[NBMAX];
__device__ volatile int g_bflag[NBMAX];
__device__ int    g_hdone, g_sdone;      // phase counters; reset by k_agg
__device__ int    g_csr[EMAX + NN];

// ---------------- helpers ---------------------------------------------------
__device__ __forceinline__ void f2tf32x2(float f, uint32_t& hi, uint32_t& lo) {
    asm("cvt.rna.tf32.f32 %0, %1;" : "=r"(hi) : "f"(f));
    float d = f - __uint_as_float(hi);
    asm("cvt.rna.tf32.f32 %0, %1;" : "=r"(lo) : "f"(d));
}

__device__ __forceinline__ void mma_tf32(float* c, const uint32_t* a, const uint32_t* b) {
    asm volatile(
        "mma.sync.aligned.m16n8k8.row.col.f32.tf32.tf32.f32 "
        "{%0,%1,%2,%3}, {%4,%5,%6,%7}, {%8,%9}, {%0,%1,%2,%3};"
        : "+f"(c[0]), "+f"(c[1]), "+f"(c[2]), "+f"(c[3])
        : "r"(a[0]), "r"(a[1]), "r"(a[2]), "r"(a[3]), "r"(b[0]), "r"(b[1]));
}

__device__ __forceinline__ void ffma2(unsigned long long& acc, unsigned long long v,
                                      unsigned long long w2) {
    asm("fma.rn.f32x2 %0, %1, %2, %0;" : "+l"(acc) : "l"(v), "l"(w2));
}

__device__ __forceinline__ float ex2(float a) {
    float r;
    asm("ex2.approx.f32 %0, %1;" : "=f"(r) : "f"(a));
    return r;
}

// ---------------- GEMM: xp = x @ W^T via 3xTF32 tensor cores ----------------
// 512 threads/block, tile 128x128. 16 warps as 4(m) x 4(n); warp tile 32x32
// -> acc[2][4][4] = 32 regs/thread (natural regs ~100, no cap, no spills,
// 16 warps/SM). Warp's 32-col range == one attention head -> simple epilogue.
#define XP 20
#define WP 136
__global__ __launch_bounds__(512) void k_gemm(
    const float* __restrict__ x, const float* __restrict__ W,
    const float* __restrict__ attS, const float* __restrict__ attD, int n)
{
    __shared__ float xsh[128 * XP], xsl[128 * XP];
    __shared__ float wth[16 * WP],  wtl[16 * WP];
    __shared__ float sAttS[128], sAttD[128];
    __shared__ float sAs[128 * 4], sAd[128 * 4];

    int t = threadIdx.x;
    // prescale by log2e: exp(leaky(z)) == exp2(leaky(z*log2e)) (leaky pos-homog.)
    if (t < 128) { sAttS[t] = attS[t] * LOG2E; sAttD[t] = attD[t] * LOG2E; }

    int row0 = blockIdx.x * 128;
    int wid = t >> 5, lane = t & 31;
    int wm = wid >> 2, wn = wid & 3;      // warp coords: 4 x 4
    int g = lane >> 2, q4 = lane & 3;

    float acc[2][4][4];
#pragma unroll
    for (int mt = 0; mt < 2; mt++)
#pragma unroll
        for (int nt = 0; nt < 4; nt++)
#pragma unroll
            for (int c = 0; c < 4; c++) acc[mt][nt][c] = 0.f;

    for (int kc = 0; kc < 128; kc += 16) {
        // stage x tile [128 x 16] hi/lo: 512 float4 slots, one per thread
        {
            int r = t >> 2, q = t & 3;
            float4 v = make_float4(0.f, 0.f, 0.f, 0.f);
            if (row0 + r < n) v = *(const float4*)(x + (size_t)(row0 + r) * 128 + kc + q * 4);
            uint32_t h0, l0, h1, l1, h2, l2, h3, l3;
            f2tf32x2(v.x, h0, l0); f2tf32x2(v.y, h1, l1);
            f2tf32x2(v.z, h2, l2); f2tf32x2(v.w, h3, l3);
            float* ph = xsh + r * XP + q * 4;
            float* pl = xsl + r * XP + q * 4;
            ph[0] = __uint_as_float(h0); ph[1] = __uint_as_float(h1);
            ph[2] = __uint_as_float(h2); ph[3] = __uint_as_float(h3);
            pl[0] = __uint_as_float(l0); pl[1] = __uint_as_float(l1);
            pl[2] = __uint_as_float(l2); pl[3] = __uint_as_float(l3);
        }
        // stage W chunk transposed [16 x 128] hi/lo: one float4 per thread
        {
            int oc = t >> 2, q = t & 3;
            float4 v = *(const float4*)(W + (size_t)oc * 128 + kc + q * 4);
            uint32_t h0, l0, h1, l1, h2, l2, h3, l3;
            f2tf32x2(v.x, h0, l0); f2tf32x2(v.y, h1, l1);
            f2tf32x2(v.z, h2, l2); f2tf32x2(v.w, h3, l3);
            wth[(q * 4 + 0) * WP + oc] = __uint_as_float(h0);
            wth[(q * 4 + 1) * WP + oc] = __uint_as_float(h1);
            wth[(q * 4 + 2) * WP + oc] = __uint_as_float(h2);
            wth[(q * 4 + 3) * WP + oc] = __uint_as_float(h3);
            wtl[(q * 4 + 0) * WP + oc] = __uint_as_float(l0);
            wtl[(q * 4 + 1) * WP + oc] = __uint_as_float(l1);
            wtl[(q * 4 + 2) * WP + oc] = __uint_as_float(l2);
            wtl[(q * 4 + 3) * WP + oc] = __uint_as_float(l3);
        }
        __syncthreads();

#pragma unroll
        for (int kk = 0; kk < 16; kk += 8) {
            uint32_t ah[2][4], al[2][4];
#pragma unroll
            for (int mt = 0; mt < 2; mt++) {
                int r = wm * 32 + mt * 16 + g;
                int b0 = r * XP + kk + q4;
                ah[mt][0] = __float_as_uint(xsh[b0]);
                ah[mt][1] = __float_as_uint(xsh[b0 + 8 * XP]);
                ah[mt][2] = __float_as_uint(xsh[b0 + 4]);
                ah[mt][3] = __float_as_uint(xsh[b0 + 8 * XP + 4]);
                al[mt][0] = __float_as_uint(xsl[b0]);
                al[mt][1] = __float_as_uint(xsl[b0 + 8 * XP]);
                al[mt][2] = __float_as_uint(xsl[b0 + 4]);
                al[mt][3] = __float_as_uint(xsl[b0 + 8 * XP + 4]);
            }
#pragma unroll
            for (int nt = 0; nt < 4; nt++) {
                int col = wn * 32 + nt * 8 + g;
                int kb = (kk + q4) * WP + col;
                uint32_t bh[2], bl[2];
                bh[0] = __float_as_uint(wth[kb]);
                bh[1] = __float_as_uint(wth[kb + 4 * WP]);
                bl[0] = __float_as_uint(wtl[kb]);
                bl[1] = __float_as_uint(wtl[kb + 4 * WP]);
#pragma unroll
                for (int mt = 0; mt < 2; mt++) {
                    mma_tf32(acc[mt][nt], ah[mt], bh);
                    mma_tf32(acc[mt][nt], ah[mt], bl);
                    mma_tf32(acc[mt][nt], al[mt], bh);
                }
            }
        }
        __syncthreads();
    }

    // ---- epilogue: xp stores + per-head attention dots (head == wn) ----
#pragma unroll
    for (int mt = 0; mt < 2; mt++) {
#pragma unroll
        for (int half = 0; half < 2; half++) {
            int rl = wm * 32 + mt * 16 + half * 8 + g;
            int r = row0 + rl;
            float ps = 0.f, pd = 0.f;
#pragma unroll
            for (int nt = 0; nt < 4; nt++) {
                int cbase = wn * 32 + nt * 8 + q4 * 2;
                float v0 = acc[mt][nt][half * 2 + 0];
                float v1 = acc[mt][nt][half * 2 + 1];
                ps += v0 * sAttS[cbase] + v1 * sAttS[cbase + 1];
                pd += v0 * sAttD[cbase] + v1 * sAttD[cbase + 1];
                if (r < n)
                    *(float2*)(g_xp + (size_t)r * 128 + cbase) = make_float2(v0, v1);
            }
            // reduce over quad lanes -> full 32-col dot for head wn
            ps += __shfl_xor_sync(0xffffffffu, ps, 1);
            ps += __shfl_xor_sync(0xffffffffu, ps, 2);
            pd += __shfl_xor_sync(0xffffffffu, pd, 1);
            pd += __shfl_xor_sync(0xffffffffu, pd, 2);
            if (q4 == 0) {
                sAs[rl * 4 + wn] = ps;
                sAd[rl * 4 + wn] = pd;
            }
        }
    }
    __syncthreads();
    if (t < 128 && row0 + t < n) {
        *(float4*)(g_asrc + (size_t)(row0 + t) * 4) = *(const float4*)(sAs + t * 4);
        *(float4*)(g_adst + (size_t)(row0 + t) * 4) = *(const float4*)(sAd + t * 4);
    }
}

// ---------------- fused CSR build: hist | scan | scatter phases -------------
__global__ __launch_bounds__(256) void k_csr(
    const int* __restrict__ src, const int* __restrict__ dst,
    int n, int E, int nhist, int nscan)
{
    __shared__ int s[256];
    int t = threadIdx.x, b = blockIdx.x;

    if (b < nhist) {
        if (b == 0 && t < NBMAX) g_bflag[t] = 0;
        int e = b * 256 + t;
        if (e < E) {
            int d = __ldcs(dst + e);
            g_ord[e] = atomicAdd(&g_deg[d], 1);
        }
        __syncthreads();
        if (t == 0) { __threadfence(); atomicAdd(&g_hdone, 1); }
        return;
    }

    if (b < nhist + nscan) {
        if (t == 0) {
            while (*(volatile int*)&g_hdone < nhist) { }
            __threadfence();
        }
        __syncthreads();

        int sb = b - nhist;
        int i = sb * 256 + t;
        int v = 0;
        if (i < n) { v = g_deg[i] + 1; g_deg[i] = 0; }
        s[t] = v;
        __syncthreads();
#pragma unroll
        for (int off = 1; off < 256; off <<= 1) {
            int u = (t >= off) ? s[t - off] : 0;
            __syncthreads();
            s[t] += u;
            __syncthreads();
        }
        int incl = s[t];
        int agg  = s[255];
        if (t == 255) {
            g_bval[sb] = agg;
            __threadfence();
            g_bflag[sb] = 1;
        }
        int part = 0;
        for (int j = t; j < sb; j += 256) {
            while (g_bflag[j] == 0) { }
            part += *(volatile int*)&g_bval[j];
        }
        __syncthreads();
        s[t] = part;
        __syncthreads();
#pragma unroll
        for (int off = 128; off > 0; off >>= 1) {
            if (t < off) s[t] += s[t + off];
            __syncthreads();
        }
        int excl0 = s[0];
        if (i < n) g_rowptr[i] = excl0 + incl - v;
        if (sb == nscan - 1 && t == 255) g_rowptr[n] = excl0 + agg;
        __syncthreads();
        if (t == 0) { __threadfence(); atomicAdd(&g_sdone, 1); }
        return;
    }

    if (t == 0) {
        while (*(volatile int*)&g_sdone < nscan) { }
        __threadfence();
    }
    __syncthreads();

    int e = (b - nhist - nscan) * 256 + t;
    int total = E + n;
    if (e >= total) return;
    if (e < E) {
        int d = __ldcs(dst + e);
        int p = g_rowptr[d] + __ldcs(g_ord + e);
        g_csr[p] = __ldcs(src + e);
    } else {
        int i = e - E;
        g_csr[g_rowptr[i + 1] - 1] = i;      // self loop in last slot
    }
}

// ---------------- aggregation: one warp per destination node ----------------
__global__ __launch_bounds__(256) void k_agg(
    const float* __restrict__ bias, float* __restrict__ out, int n)
{
    // reset fused-CSR phase counters for the next graph replay
    if (blockIdx.x == 0 && threadIdx.x == 0) { g_hdone = 0; g_sdone = 0; }

    int warp = (blockIdx.x * blockDim.x + threadIdx.x) >> 5;
    int lane = threadIdx.x & 31;
    if (warp >= n) return;
    int nd = warp;
    int h = lane >> 3;

    int begin = g_rowptr[nd], end = g_rowptr[nd + 1];
    float adh = g_adst[nd * 4 + h];

    unsigned long long acc01 = 0ull, acc23 = 0ull;   // packed f32x2 accumulators
    float den = 0.f;
    const float* xpb = g_xp + lane * 4;

    int i = begin;
    // head: align to 16B so the int4 csr loads below are aligned
    for (; i < end && (i & 3); i++) {
        int s0 = g_csr[i];
        float a0 = g_asrc[s0 * 4 + h] + adh;
        ulonglong2 u0 = *(const ulonglong2*)(xpb + (size_t)s0 * 128);
        a0 = fmaxf(a0, NEG * a0);
        float w0 = ex2(a0);
        unsigned long long ww;
        asm("mov.b64 %0, {%1, %1};" : "=l"(ww) : "f"(w0));
        ffma2(acc01, u0.x, ww); ffma2(acc23, u0.y, ww);
        den += w0;
    }
    for (; i + 4 <= end; i += 4) {
        int4 sv = *(const int4*)(g_csr + i);          // 1x LDG.128 for 4 edges
        float a0 = g_asrc[sv.x * 4 + h] + adh;
        float a1 = g_asrc[sv.y * 4 + h] + adh;
        float a2 = g_asrc[sv.z * 4 + h] + adh;
        float a3 = g_asrc[sv.w * 4 + h] + adh;
        ulonglong2 u0 = *(const ulonglong2*)(xpb + (size_t)sv.x * 128);
        ulonglong2 u1 = *(const ulonglong2*)(xpb + (size_t)sv.y * 128);
        ulonglong2 u2 = *(const ulonglong2*)(xpb + (size_t)sv.z * 128);
        ulonglong2 u3 = *(const ulonglong2*)(xpb + (size_t)sv.w * 128);
        a0 = fmaxf(a0, NEG * a0);
        a1 = fmaxf(a1, NEG * a1);
        a2 = fmaxf(a2, NEG * a2);
        a3 = fmaxf(a3, NEG * a3);
        float w0 = ex2(a0), w1 = ex2(a1), w2 = ex2(a2), w3 = ex2(a3);
        unsigned long long ww;
        asm("mov.b64 %0, {%1, %1};" : "=l"(ww) : "f"(w0));
        ffma2(acc01, u0.x, ww); ffma2(acc23, u0.y, ww);
        asm("mov.b64 %0, {%1, %1};" : "=l"(ww) : "f"(w1));
        ffma2(acc01, u1.x, ww); ffma2(acc23, u1.y, ww);
        asm("mov.b64 %0, {%1, %1};" : "=l"(ww) : "f"(w2));
        ffma2(acc01, u2.x, ww); ffma2(acc23, u2.y, ww);
        asm("mov.b64 %0, {%1, %1};" : "=l"(ww) : "f"(w3));
        ffma2(acc01, u3.x, ww); ffma2(acc23, u3.y, ww);
        den += (w0 + w1) + (w2 + w3);
    }
    for (; i < end; i++) {
        int s0 = g_csr[i];
        float a0 = g_asrc[s0 * 4 + h] + adh;
        ulonglong2 u0 = *(const ulonglong2*)(xpb + (size_t)s0 * 128);
        a0 = fmaxf(a0, NEG * a0);
        float w0 = ex2(a0);
        unsigned long long ww;
        asm("mov.b64 %0, {%1, %1};" : "=l"(ww) : "f"(w0));
        ffma2(acc01, u0.x, ww); ffma2(acc23, u0.y, ww);
        den += w0;
    }

    float ax, ay, az, aw;
    asm("mov.b64 {%0, %1}, %2;" : "=f"(ax), "=f"(ay) : "l"(acc01));
    asm("mov.b64 {%0, %1}, %2;" : "=f"(az), "=f"(aw) : "l"(acc23));

    float inv = 1.0f / (den + 1e-16f);
    float4 bb = ((const float4*)bias)[lane];
    float4 o;
    o.x = ax * inv + bb.x;
    o.y = ay * inv + bb.y;
    o.z = az * inv + bb.z;
    o.w = aw * inv + bb.w;
    o.x = o.x > 0.f ? o.x : (__expf(o.x) - 1.f);
    o.y = o.y > 0.f ? o.y : (__expf(o.y) - 1.f);
    o.z = o.z > 0.f ? o.z : (__expf(o.z) - 1.f);
    o.w = o.w > 0.f ? o.w : (__expf(o.w) - 1.f);
    ((float4*)out)[(size_t)nd * 32 + lane] = o;
}

// ---------------- launch: GEMM overlapped with fused CSR build --------------
extern "C" void kernel_launch(void* const* d_in, const int* in_sizes, int n_in,
                              void* d_out, int out_size)
{
    const float* x    = (const float*)d_in[0];
    const float* W    = (const float*)d_in[1];
    const float* attS = (const float*)d_in[2];
    const float* attD = (const float*)d_in[3];
    const float* bias = (const float*)d_in[4];
    const int*   ei   = (const int*)d_in[5];

    int n = in_sizes[0] / FH;        // 50000
    int E = in_sizes[5] / 2;         // 800000
    const int* src = ei;
    const int* dst = ei + E;

    int nhist = (E + 255) / 256;                 // 3125
    int nscan = (n + 255) / 256;                 // 196
    int nscat = (E + n + 255) / 256;             // 3321

    // host-side resources, created once (host objects only; no device memory)
    static cudaStream_t s_side = nullptr;
    static cudaEvent_t  ev_fork = nullptr, ev_join = nullptr;
    if (s_side == nullptr) {
        cudaStreamCreateWithFlags(&s_side, cudaStreamNonBlocking);
        cudaEventCreateWithFlags(&ev_fork, cudaEventDisableTiming);
        cudaEventCreateWithFlags(&ev_join, cudaEventDisableTiming);
    }

    // fork: GEMM on side stream, fused CSR build on main stream
    cudaEventRecord(ev_fork, 0);
    cudaStreamWaitEvent(s_side, ev_fork, 0);
    k_gemm<<<(n + 127) / 128, 512, 0, s_side>>>(x, W, attS, attD, n);
    cudaEventRecord(ev_join, s_side);

    k_csr<<<nhist + nscan + nscat, 256>>>(src, dst, n, E, nhist, nscan);

    // join: aggregation needs both GEMM outputs and CSR
    cudaStreamWaitEvent(0, ev_join, 0);
    k_agg<<<(n * 32 + 255) / 256, 256>>>(bias, (float*)d_out, n);
}

// round 14
// speedup vs baseline: 1.7200x; 1.3089x over previous
#include <cuda_runtime.h>
#include <cuda_fp16.h>
#include <math.h>
#include <stdint.h>

#define NN    50000
#define FH    128      // H*C
#define NH    4
#define EMAX  800000
#define NEG   0.2f
#define NBMAX 256      // >= ceil(NN/256) scan blocks
#define LOG2E 1.44269504088896f

// ---------------- scratch (static device globals; no runtime alloc) --------
__device__ float  g_xp[NN * FH];         // projected features fp32 [N][128]
__device__ float  g_asrc[NN * NH];       // prescaled by log2e
__device__ float  g_adst[NN * NH];       // prescaled by log2e
__device__ int    g_deg[NN];             // real-edge counts; re-zeroed in scan
__device__ int    g_ord[EMAX];           // per-edge ordinal within its dst row
__device__ int    g_rowptr[NN + 1];
__device__ int    g_bval[NBMAX];
__device__ volatile int g_bflag[NBMAX];
__device__ int    g_hdone, g_sdone;      // phase counters; reset by k_agg
__device__ int    g_csr[EMAX + NN];

// ---------------- helpers ---------------------------------------------------
__device__ __forceinline__ void mma_f16(float* c, const uint32_t* a,
                                        uint32_t b0, uint32_t b1) {
    asm volatile(
        "mma.sync.aligned.m16n8k16.row.col.f32.f16.f16.f32 "
        "{%0,%1,%2,%3}, {%4,%5,%6,%7}, {%8,%9}, {%0,%1,%2,%3};"
        : "+f"(c[0]), "+f"(c[1]), "+f"(c[2]), "+f"(c[3])
        : "r"(a[0]), "r"(a[1]), "r"(a[2]), "r"(a[3]), "r"(b0), "r"(b1));
}

__device__ __forceinline__ void ffma2(unsigned long long& acc, unsigned long long v,
                                      unsigned long long w2) {
    asm("fma.rn.f32x2 %0, %1, %2, %0;" : "+l"(acc) : "l"(v), "l"(w2));
}

__device__ __forceinline__ float ex2(float a) {
    float r;
    asm("ex2.approx.f32 %0, %1;" : "=f"(r) : "f"(a));
    return r;
}

// ---------------- GEMM: xp = x @ W^T via fp16 m16n8k16 tensor cores ---------
// 512 threads, tile 128x128, BK=16. 16 warps as 4(m) x 4(n), warp tile 32x32.
// fp16 operands: one MMA covers k=16; half2-packed LDS halves the load count.
// Inner loop per k-chunk per warp: 16 LDS + 8 MMA (was 64 LDS + 48 MMA).
// W staged [oc][k] halves -> direct copy (no transpose), b-frag pairs contiguous.
#define XPH 24    // smem pitch in halves (48B = 12 banks -> conflict-free frags)
__global__ __launch_bounds__(512) void k_gemm(
    const float* __restrict__ x, const float* __restrict__ W,
    const float* __restrict__ attS, const float* __restrict__ attD, int n)
{
    __shared__ __half xsh[128 * XPH];
    __shared__ __half wsh[128 * XPH];
    __shared__ float sAttS[128], sAttD[128];
    __shared__ float sAs[128 * 4], sAd[128 * 4];

    int t = threadIdx.x;
    // prescale by log2e: exp(leaky(z)) == exp2(leaky(z*log2e)) (leaky pos-homog.)
    if (t < 128) { sAttS[t] = attS[t] * LOG2E; sAttD[t] = attD[t] * LOG2E; }

    int row0 = blockIdx.x * 128;
    int wid = t >> 5, lane = t & 31;
    int wm = wid >> 2, wn = wid & 3;      // warp coords: 4 x 4
    int g = lane >> 2, q4 = lane & 3;

    float acc[2][4][4];
#pragma unroll
    for (int mt = 0; mt < 2; mt++)
#pragma unroll
        for (int nt = 0; nt < 4; nt++)
#pragma unroll
            for (int c = 0; c < 4; c++) acc[mt][nt][c] = 0.f;

    for (int kc = 0; kc < 128; kc += 16) {
        // stage x tile [128 rows x 16 k] as fp16: one float4 -> 2 half2 per thread
        {
            int r = t >> 2, q = t & 3;
            float4 v = make_float4(0.f, 0.f, 0.f, 0.f);
            if (row0 + r < n) v = *(const float4*)(x + (size_t)r * 128 + (size_t)row0 * 128 + kc + q * 4);
            __half2* p = (__half2*)(xsh + r * XPH + q * 4);
            p[0] = __floats2half2_rn(v.x, v.y);
            p[1] = __floats2half2_rn(v.z, v.w);
        }
        // stage W tile [128 oc x 16 k] as fp16: direct copy, k contiguous
        {
            int oc = t >> 2, q = t & 3;
            float4 v = *(const float4*)(W + (size_t)oc * 128 + kc + q * 4);
            __half2* p = (__half2*)(wsh + oc * XPH + q * 4);
            p[0] = __floats2half2_rn(v.x, v.y);
            p[1] = __floats2half2_rn(v.z, v.w);
        }
        __syncthreads();

        // one m16n8k16 MMA per (mt,nt) covers the whole k-chunk
        uint32_t a[2][4];
#pragma unroll
        for (int mt = 0; mt < 2; mt++) {
            const __half* base = xsh + (wm * 32 + mt * 16 + g) * XPH + 2 * q4;
            a[mt][0] = *(const uint32_t*)(base);
            a[mt][1] = *(const uint32_t*)(base + 8 * XPH);
            a[mt][2] = *(const uint32_t*)(base + 8);
            a[mt][3] = *(const uint32_t*)(base + 8 * XPH + 8);
        }
#pragma unroll
        for (int nt = 0; nt < 4; nt++) {
            const __half* bb = wsh + (wn * 32 + nt * 8 + g) * XPH + 2 * q4;
            uint32_t b0 = *(const uint32_t*)(bb);
            uint32_t b1 = *(const uint32_t*)(bb + 8);
#pragma unroll
            for (int mt = 0; mt < 2; mt++)
                mma_f16(acc[mt][nt], a[mt], b0, b1);
        }
        __syncthreads();
    }

    // ---- epilogue: xp stores + per-head attention dots (head == wn) ----
#pragma unroll
    for (int mt = 0; mt < 2; mt++) {
#pragma unroll
        for (int half = 0; half < 2; half++) {
            int rl = wm * 32 + mt * 16 + half * 8 + g;
            int r = row0 + rl;
            float ps = 0.f, pd = 0.f;
#pragma unroll
            for (int nt = 0; nt < 4; nt++) {
                int cbase = wn * 32 + nt * 8 + q4 * 2;
                float v0 = acc[mt][nt][half * 2 + 0];
                float v1 = acc[mt][nt][half * 2 + 1];
                ps += v0 * sAttS[cbase] + v1 * sAttS[cbase + 1];
                pd += v0 * sAttD[cbase] + v1 * sAttD[cbase + 1];
                if (r < n)
                    *(float2*)(g_xp + (size_t)r * 128 + cbase) = make_float2(v0, v1);
            }
            ps += __shfl_xor_sync(0xffffffffu, ps, 1);
            ps += __shfl_xor_sync(0xffffffffu, ps, 2);
            pd += __shfl_xor_sync(0xffffffffu, pd, 1);
            pd += __shfl_xor_sync(0xffffffffu, pd, 2);
            if (q4 == 0) {
                sAs[rl * 4 + wn] = ps;
                sAd[rl * 4 + wn] = pd;
            }
        }
    }
    __syncthreads();
    if (t < 128 && row0 + t < n) {
        *(float4*)(g_asrc + (size_t)(row0 + t) * 4) = *(const float4*)(sAs + t * 4);
        *(float4*)(g_adst + (size_t)(row0 + t) * 4) = *(const float4*)(sAd + t * 4);
    }
}

// ---------------- fused CSR build: hist | scan | scatter phases -------------
__global__ __launch_bounds__(256) void k_csr(
    const int* __restrict__ src, const int* __restrict__ dst,
    int n, int E, int nhist, int nscan)
{
    __shared__ int s[256];
    int t = threadIdx.x, b = blockIdx.x;

    if (b < nhist) {
        if (b == 0 && t < NBMAX) g_bflag[t] = 0;
        int e = b * 256 + t;
        if (e < E) {
            int d = __ldcs(dst + e);
            g_ord[e] = atomicAdd(&g_deg[d], 1);
        }
        __syncthreads();
        if (t == 0) { __threadfence(); atomicAdd(&g_hdone, 1); }
        return;
    }

    if (b < nhist + nscan) {
        if (t == 0) {
            while (*(volatile int*)&g_hdone < nhist) { }
            __threadfence();
        }
        __syncthreads();

        int sb = b - nhist;
        int i = sb * 256 + t;
        int v = 0;
        if (i < n) { v = g_deg[i] + 1; g_deg[i] = 0; }
        s[t] = v;
        __syncthreads();
#pragma unroll
        for (int off = 1; off < 256; off <<= 1) {
            int u = (t >= off) ? s[t - off] : 0;
            __syncthreads();
            s[t] += u;
            __syncthreads();
        }
        int incl = s[t];
        int agg  = s[255];
        if (t == 255) {
            g_bval[sb] = agg;
            __threadfence();
            g_bflag[sb] = 1;
        }
        int part = 0;
        for (int j = t; j < sb; j += 256) {
            while (g_bflag[j] == 0) { }
            part += *(volatile int*)&g_bval[j];
        }
        __syncthreads();
        s[t] = part;
        __syncthreads();
#pragma unroll
        for (int off = 128; off > 0; off >>= 1) {
            if (t < off) s[t] += s[t + off];
            __syncthreads();
        }
        int excl0 = s[0];
        if (i < n) g_rowptr[i] = excl0 + incl - v;
        if (sb == nscan - 1 && t == 255) g_rowptr[n] = excl0 + agg;
        __syncthreads();
        if (t == 0) { __threadfence(); atomicAdd(&g_sdone, 1); }
        return;
    }

    if (t == 0) {
        while (*(volatile int*)&g_sdone < nscan) { }
        __threadfence();
    }
    __syncthreads();

    int e = (b - nhist - nscan) * 256 + t;
    int total = E + n;
    if (e >= total) return;
    if (e < E) {
        int d = __ldcs(dst + e);
        int p = g_rowptr[d] + __ldcs(g_ord + e);
        g_csr[p] = __ldcs(src + e);
    } else {
        int i = e - E;
        g_csr[g_rowptr[i + 1] - 1] = i;      // self loop in last slot
    }
}

// ---------------- aggregation: one warp per destination node ----------------
__global__ __launch_bounds__(256) void k_agg(
    const float* __restrict__ bias, float* __restrict__ out, int n)
{
    // reset fused-CSR phase counters for the next graph replay
    if (blockIdx.x == 0 && threadIdx.x == 0) { g_hdone = 0; g_sdone = 0; }

    int warp = (blockIdx.x * blockDim.x + threadIdx.x) >> 5;
    int lane = threadIdx.x & 31;
    if (warp >= n) return;
    int nd = warp;
    int h = lane >> 3;

    int begin = g_rowptr[nd], end = g_rowptr[nd + 1];
    float adh = g_adst[nd * 4 + h];

    unsigned long long acc01 = 0ull, acc23 = 0ull;   // packed f32x2 accumulators
    float den = 0.f;
    const float* xpb = g_xp + lane * 4;

    int i = begin;
    // head: align to 16B so the int4 csr loads below are aligned
    for (; i < end && (i & 3); i++) {
        int s0 = g_csr[i];
        float a0 = g_asrc[s0 * 4 + h] + adh;
        ulonglong2 u0 = *(const ulonglong2*)(xpb + (size_t)s0 * 128);
        a0 = fmaxf(a0, NEG * a0);
        float w0 = ex2(a0);
        unsigned long long ww;
        asm("mov.b64 %0, {%1, %1};" : "=l"(ww) : "f"(w0));
        ffma2(acc01, u0.x, ww); ffma2(acc23, u0.y, ww);
        den += w0;
    }
    for (; i + 4 <= end; i += 4) {
        int4 sv = *(const int4*)(g_csr + i);          // 1x LDG.128 for 4 edges
        float a0 = g_asrc[sv.x * 4 + h] + adh;
        float a1 = g_asrc[sv.y * 4 + h] + adh;
        float a2 = g_asrc[sv.z * 4 + h] + adh;
        float a3 = g_asrc[sv.w * 4 + h] + adh;
        ulonglong2 u0 = *(const ulonglong2*)(xpb + (size_t)sv.x * 128);
        ulonglong2 u1 = *(const ulonglong2*)(xpb + (size_t)sv.y * 128);
        ulonglong2 u2 = *(const ulonglong2*)(xpb + (size_t)sv.z * 128);
        ulonglong2 u3 = *(const ulonglong2*)(xpb + (size_t)sv.w * 128);
        a0 = fmaxf(a0, NEG * a0);
        a1 = fmaxf(a1, NEG * a1);
        a2 = fmaxf(a2, NEG * a2);
        a3 = fmaxf(a3, NEG * a3);
        float w0 = ex2(a0), w1 = ex2(a1), w2 = ex2(a2), w3 = ex2(a3);
        unsigned long long ww;
        asm("mov.b64 %0, {%1, %1};" : "=l"(ww) : "f"(w0));
        ffma2(acc01, u0.x, ww); ffma2(acc23, u0.y, ww);
        asm("mov.b64 %0, {%1, %1};" : "=l"(ww) : "f"(w1));
        ffma2(acc01, u1.x, ww); ffma2(acc23, u1.y, ww);
        asm("mov.b64 %0, {%1, %1};" : "=l"(ww) : "f"(w2));
        ffma2(acc01, u2.x, ww); ffma2(acc23, u2.y, ww);
        asm("mov.b64 %0, {%1, %1};" : "=l"(ww) : "f"(w3));
        ffma2(acc01, u3.x, ww); ffma2(acc23, u3.y, ww);
        den += (w0 + w1) + (w2 + w3);
    }
    for (; i < end; i++) {
        int s0 = g_csr[i];
        float a0 = g_asrc[s0 * 4 + h] + adh;
        ulonglong2 u0 = *(const ulonglong2*)(xpb + (size_t)s0 * 128);
        a0 = fmaxf(a0, NEG * a0);
        float w0 = ex2(a0);
        unsigned long long ww;
        asm("mov.b64 %0, {%1, %1};" : "=l"(ww) : "f"(w0));
        ffma2(acc01, u0.x, ww); ffma2(acc23, u0.y, ww);
        den += w0;
    }

    float ax, ay, az, aw;
    asm("mov.b64 {%0, %1}, %2;" : "=f"(ax), "=f"(ay) : "l"(acc01));
    asm("mov.b64 {%0, %1}, %2;" : "=f"(az), "=f"(aw) : "l"(acc23));

    float inv = 1.0f / (den + 1e-16f);
    float4 bb = ((const float4*)bias)[lane];
    float4 o;
    o.x = ax * inv + bb.x;
    o.y = ay * inv + bb.y;
    o.z = az * inv + bb.z;
    o.w = aw * inv + bb.w;
    o.x = o.x > 0.f ? o.x : (__expf(o.x) - 1.f);
    o.y = o.y > 0.f ? o.y : (__expf(o.y) - 1.f);
    o.z = o.z > 0.f ? o.z : (__expf(o.z) - 1.f);
    o.w = o.w > 0.f ? o.w : (__expf(o.w) - 1.f);
    ((float4*)out)[(size_t)nd * 32 + lane] = o;
}

// ---------------- launch: GEMM overlapped with fused CSR build --------------
extern "C" void kernel_launch(void* const* d_in, const int* in_sizes, int n_in,
                              void* d_out, int out_size)
{
    const float* x    = (const float*)d_in[0];
    const float* W    = (const float*)d_in[1];
    const float* attS = (const float*)d_in[2];
    const float* attD = (const float*)d_in[3];
    const float* bias = (const float*)d_in[4];
    const int*   ei   = (const int*)d_in[5];

    int n = in_sizes[0] / FH;        // 50000
    int E = in_sizes[5] / 2;         // 800000
    const int* src = ei;
    const int* dst = ei + E;

    int nhist = (E + 255) / 256;                 // 3125
    int nscan = (n + 255) / 256;                 // 196
    int nscat = (E + n + 255) / 256;             // 3321

    // host-side resources, created once (host objects only; no device memory)
    static cudaStream_t s_side = nullptr;
    static cudaEvent_t  ev_fork = nullptr, ev_join = nullptr;
    if (s_side == nullptr) {
        cudaStreamCreateWithFlags(&s_side, cudaStreamNonBlocking);
        cudaEventCreateWithFlags(&ev_fork, cudaEventDisableTiming);
        cudaEventCreateWithFlags(&ev_join, cudaEventDisableTiming);
    }

    // fork: GEMM on side stream, fused CSR build on main stream
    cudaEventRecord(ev_fork, 0);
    cudaStreamWaitEvent(s_side, ev_fork, 0);
    k_gemm<<<(n + 127) / 128, 512, 0, s_side>>>(x, W, attS, attD, n);
    cudaEventRecord(ev_join, s_side);

    k_csr<<<nhist + nscan + nscat, 256>>>(src, dst, n, E, nhist, nscan);

    // join: aggregation needs both GEMM outputs and CSR
    cudaStreamWaitEvent(0, ev_join, 0);
    k_agg<<<(n * 32 + 255) / 256, 256>>>(bias, (float*)d_out, n);
}